// round 10
// baseline (speedup 1.0000x reference)
#include <cuda_runtime.h>

#define NBX 168
#define NBY 480
#define NBL 6
#define XY  (NBX * NBY)
#define MAPSZ (NBX * NBY * NBL)
#define EXT 2
#define WW  (2 * EXT + 1)

static __device__ float g_dem[MAPSZ];     // [type][x][y]  (type-major)
static __device__ float g_compat[MAPSZ];  // [type][x][y]

__device__ __forceinline__ float inv_sqrt2() { return 0.70710678118654752440f; }

// Compute one axis' 5 truncated-Gaussian weights (6 erf evals, shared edges).
__device__ __forceinline__ void axis_weights(float c, int b0, float* g) {
    float e0 = erff(((float)b0 - c) * inv_sqrt2());
#pragma unroll
    for (int i = 0; i < WW; i++) {
        float e1 = erff(((float)(b0 + i + 1) - c) * inv_sqrt2());
        g[i] = 0.5f * (e1 - e0);
        e0 = e1;
    }
}

// Add 5 contiguous values to row[0..4] with vectorized REDs when possible.
// Row address parity equals by0 parity: g_dem base is 16B-aligned, XY/NBY even.
__device__ __forceinline__ void row_scatter5(float* row, int parity,
                                             float w0, float w1, float w2,
                                             float w3, float w4) {
#if __CUDA_ARCH__ >= 900
    if (parity == 0) {
        atomicAdd(reinterpret_cast<float2*>(row),     make_float2(w0, w1));
        atomicAdd(reinterpret_cast<float2*>(row + 2), make_float2(w2, w3));
        atomicAdd(row + 4, w4);
    } else {
        atomicAdd(row, w0);
        atomicAdd(reinterpret_cast<float2*>(row + 1), make_float2(w1, w2));
        atomicAdd(reinterpret_cast<float2*>(row + 3), make_float2(w3, w4));
    }
#else
    atomicAdd(row,     w0);
    atomicAdd(row + 1, w1);
    atomicAdd(row + 2, w2);
    atomicAdd(row + 3, w3);
    atomicAdd(row + 4, w4);
#endif
}

// Load 5 contiguous floats from row[0..4] with 64-bit loads when possible.
__device__ __forceinline__ void row_gather5(const float* row, int parity,
                                            float* f) {
    if (parity == 0) {
        float2 a = __ldg(reinterpret_cast<const float2*>(row));
        float2 b = __ldg(reinterpret_cast<const float2*>(row + 2));
        f[0] = a.x; f[1] = a.y; f[2] = b.x; f[3] = b.y;
        f[4] = __ldg(row + 4);
    } else {
        f[0] = __ldg(row);
        float2 a = __ldg(reinterpret_cast<const float2*>(row + 1));
        float2 b = __ldg(reinterpret_cast<const float2*>(row + 3));
        f[1] = a.x; f[2] = a.y; f[3] = b.x; f[4] = b.y;
    }
}

// ---------------------------------------------------------------------------
// Kernel 1: zero demand map + output buffer (harness poisons d_out to 0xAA).
// ---------------------------------------------------------------------------
__global__ void zero_kernel(float4* __restrict__ out4, int n_out4) {
    int i = blockIdx.x * blockDim.x + threadIdx.x;
    int stride = gridDim.x * blockDim.x;
    float4 z = make_float4(0.f, 0.f, 0.f, 0.f);
    float4* dem4 = reinterpret_cast<float4*>(g_dem);
    for (int j = i; j < MAPSZ / 4; j += stride) dem4[j] = z;
    for (int j = i; j < n_out4; j += stride) out4[j] = z;
}

// ---------------------------------------------------------------------------
// One scatter instance (inlined twice per thread for ILP).
// ---------------------------------------------------------------------------
__device__ __forceinline__ void scatter_one(const float* __restrict__ pos,
                                            const float* __restrict__ nsx,
                                            const float* __restrict__ nsy,
                                            const int*  __restrict__ lut_indices,
                                            const int*  __restrict__ lut_type,
                                            int n, int l) {
    int idx = __ldg(lut_indices + l);

    float sx = __ldg(nsx + idx);
    float sy = __ldg(nsy + idx);
    float cx = __ldg(pos + idx)     + 0.5f * sx;   // INV_STDX = 1
    float cy = __ldg(pos + n + idx) + 0.5f * sy;   // INV_STDY = 1

    int bx0 = __float2int_rd(cx) - EXT;
    int by0 = __float2int_rd(cy) - EXT;

    float gx[WW], gy[WW];
    axis_weights(cx, bx0, gx);
    axis_weights(cy, by0, gy);

    int ilo = max(0, -bx0), ihi = min(WW, NBX - bx0);
    int jlo = max(0, -by0), jhi = min(WW, NBY - by0);

    float area = sx * sy;
    int t = __ldg(lut_type + idx);
    float* plane = g_dem + t * XY;

    if (jlo == 0 && jhi == WW) {
        int parity = by0 & 1;
#pragma unroll
        for (int i = 0; i < WW; i++) {
            if (i < ilo || i >= ihi) continue;
            float wi = area * gx[i];
            float* row = plane + (bx0 + i) * NBY + by0;
            row_scatter5(row, parity,
                         wi * gy[0], wi * gy[1], wi * gy[2],
                         wi * gy[3], wi * gy[4]);
        }
    } else {
#pragma unroll
        for (int i = 0; i < WW; i++) {
            if (i < ilo || i >= ihi) continue;
            float wi = area * gx[i];
            float* row = plane + (bx0 + i) * NBY + by0;
#pragma unroll
            for (int j = 0; j < WW; j++) {
                if (j < jlo || j >= jhi) continue;
                atomicAdd(row + j, wi * gy[j]);
            }
        }
    }
}

__global__ void __launch_bounds__(256)
scatter_kernel(const float* __restrict__ pos,
               const float* __restrict__ nsx,
               const float* __restrict__ nsy,
               const int*  __restrict__ lut_indices,
               const int*  __restrict__ lut_type,
               int n, int L, int H) {
    int l = blockIdx.x * blockDim.x + threadIdx.x;
    if (l >= H) return;
    scatter_one(pos, nsx, nsy, lut_indices, lut_type, n, l);
    int l2 = l + H;
    if (l2 < L)
        scatter_one(pos, nsx, nsy, lut_indices, lut_type, n, l2);
}

// ---------------------------------------------------------------------------
// Kernel 3: compat[t][xy] = sum_l frac[t][l] * dem[l][xy]   (6x6, tiny)
// ---------------------------------------------------------------------------
__global__ void compat_kernel(const int* __restrict__ frac) {
    int xy = blockIdx.x * blockDim.x + threadIdx.x;
    if (xy >= XY) return;
    float d[NBL];
#pragma unroll
    for (int l = 0; l < NBL; l++) d[l] = g_dem[l * XY + xy];
#pragma unroll
    for (int t = 0; t < NBL; t++) {
        float acc = 0.0f;
#pragma unroll
        for (int l = 0; l < NBL; l++)
            acc += d[l] * (float)__ldg(frac + t * NBL + l);
        g_compat[t * XY + xy] = acc;
    }
}

// ---------------------------------------------------------------------------
// One gather instance (inlined twice per thread for ILP).
// ---------------------------------------------------------------------------
__device__ __forceinline__ void gather_one(const float* __restrict__ pos,
                                           const float* __restrict__ nsx,
                                           const float* __restrict__ nsy,
                                           const int*  __restrict__ lut_indices,
                                           const int*  __restrict__ lut_type,
                                           float* __restrict__ out,
                                           int n, int l) {
    int idx = __ldg(lut_indices + l);

    float sx = __ldg(nsx + idx);
    float sy = __ldg(nsy + idx);
    float cx = __ldg(pos + idx)     + 0.5f * sx;
    float cy = __ldg(pos + n + idx) + 0.5f * sy;

    int bx0 = __float2int_rd(cx) - EXT;
    int by0 = __float2int_rd(cy) - EXT;

    float gx[WW], gy[WW];
    axis_weights(cx, bx0, gx);
    axis_weights(cy, by0, gy);

    int ilo = max(0, -bx0), ihi = min(WW, NBX - bx0);
    int jlo = max(0, -by0), jhi = min(WW, NBY - by0);

    int t = __ldg(lut_type + idx);
    const float* plane = g_compat + t * XY;

    float acc = 0.0f;
    if (jlo == 0 && jhi == WW) {
        int parity = by0 & 1;
#pragma unroll
        for (int i = 0; i < WW; i++) {
            if (i < ilo || i >= ihi) continue;
            const float* row = plane + (bx0 + i) * NBY + by0;
            float f[WW];
            row_gather5(row, parity, f);
            float ai = f[0] * gy[0] + f[1] * gy[1] + f[2] * gy[2]
                     + f[3] * gy[3] + f[4] * gy[4];
            acc += gx[i] * ai;
        }
    } else {
#pragma unroll
        for (int i = 0; i < WW; i++) {
            if (i < ilo || i >= ihi) continue;
            const float* row = plane + (bx0 + i) * NBY + by0;
            float ai = 0.0f;
#pragma unroll
            for (int j = 0; j < WW; j++) {
                if (j < jlo || j >= jhi) continue;
                ai += gy[j] * __ldg(row + j);
            }
            acc += gx[i] * ai;
        }
    }

    // STDXY = 1, SLICE_CAPACITY = 16
    out[idx] = acc * (1.0f / 16.0f);
}

__global__ void __launch_bounds__(256)
gather_kernel(const float* __restrict__ pos,
              const float* __restrict__ nsx,
              const float* __restrict__ nsy,
              const int*  __restrict__ lut_indices,
              const int*  __restrict__ lut_type,
              float* __restrict__ out,
              int n, int L, int H) {
    int l = blockIdx.x * blockDim.x + threadIdx.x;
    if (l >= H) return;
    gather_one(pos, nsx, nsy, lut_indices, lut_type, out, n, l);
    int l2 = l + H;
    if (l2 < L)
        gather_one(pos, nsx, nsy, lut_indices, lut_type, out, n, l2);
}

// ---------------------------------------------------------------------------
extern "C" void kernel_launch(void* const* d_in, const int* in_sizes, int n_in,
                              void* d_out, int out_size) {
    const float* pos         = (const float*)d_in[0];
    const float* node_size_x = (const float*)d_in[1];
    const float* node_size_y = (const float*)d_in[2];
    const int*   lut_indices = (const int*)  d_in[3];
    const int*   lut_type    = (const int*)  d_in[4];
    const int*   lut_frac    = (const int*)  d_in[5];

    int n = in_sizes[1];   // number of nodes (N)
    int L = in_sizes[3];   // number of LUT instances
    int H = (L + 1) / 2;   // instances handled per "lane" (2 per thread)

    zero_kernel<<<1024, 256>>>((float4*)d_out, out_size / 4);

    int blocks = (H + 255) / 256;
    scatter_kernel<<<blocks, 256>>>(pos, node_size_x, node_size_y,
                                    lut_indices, lut_type, n, L, H);

    compat_kernel<<<(XY + 255) / 256, 256>>>(lut_frac);

    gather_kernel<<<blocks, 256>>>(pos, node_size_x, node_size_y,
                                   lut_indices, lut_type, (float*)d_out, n, L, H);
}

// round 13
// speedup vs baseline: 1.2837x; 1.2837x over previous
#include <cuda_runtime.h>

#define NBX 168
#define NBY 480
#define NBL 6
#define XY  (NBX * NBY)
#define MAPSZ (NBX * NBY * NBL)
#define EXT 2
#define WW  (2 * EXT + 1)

static __device__ __align__(16) float g_dem[MAPSZ];     // [type][x][y]
static __device__ __align__(16) float g_compat[MAPSZ];  // [type][x][y]

__device__ __forceinline__ float inv_sqrt2() { return 0.70710678118654752440f; }

// Compute one axis' 5 truncated-Gaussian weights (6 erf evals, shared edges).
__device__ __forceinline__ void axis_weights(float c, int b0, float* g) {
    float e0 = erff(((float)b0 - c) * inv_sqrt2());
#pragma unroll
    for (int i = 0; i < WW; i++) {
        float e1 = erff(((float)(b0 + i + 1) - c) * inv_sqrt2());
        g[i] = 0.5f * (e1 - e0);
        e0 = e1;
    }
}

// Build 8-wide zero-padded weight vector: w[a..a+4] = gy[0..4], rest 0.
// a in [0,3]; constant indices per switch case keep everything in registers.
__device__ __forceinline__ void build_wpad(const float* gy, int a, float* w) {
#pragma unroll
    for (int s = 0; s < 8; s++) w[s] = 0.0f;
    switch (a) {
    case 0:
#pragma unroll
        for (int k = 0; k < WW; k++) w[k]     = gy[k];
        break;
    case 1:
#pragma unroll
        for (int k = 0; k < WW; k++) w[k + 1] = gy[k];
        break;
    case 2:
#pragma unroll
        for (int k = 0; k < WW; k++) w[k + 2] = gy[k];
        break;
    default:
#pragma unroll
        for (int k = 0; k < WW; k++) w[k + 3] = gy[k];
        break;
    }
}

// ---------------------------------------------------------------------------
// Kernel 1: zero demand map + output buffer (harness poisons d_out to 0xAA).
// ---------------------------------------------------------------------------
__global__ void zero_kernel(float4* __restrict__ out4, int n_out4) {
    int i = blockIdx.x * blockDim.x + threadIdx.x;
    int stride = gridDim.x * blockDim.x;
    float4 z = make_float4(0.f, 0.f, 0.f, 0.f);
    float4* dem4 = reinterpret_cast<float4*>(g_dem);
    for (int j = i; j < MAPSZ / 4; j += stride) dem4[j] = z;
    for (int j = i; j < n_out4; j += stride) out4[j] = z;
}

// ---------------------------------------------------------------------------
// One scatter instance. Fast path (y-interior, ~99%): by0 in [0,475] so the
// 4-aligned 8-element window [b4, b4+8) always fits inside the row ->
// exactly 2 float4 atomics per row. Extra lanes add +0.0f (bit-exact: all
// dem values are >= +0.0 and x + (+0.0) == x).
// ---------------------------------------------------------------------------
__device__ __forceinline__ void scatter_one(const float* __restrict__ pos,
                                            const float* __restrict__ nsx,
                                            const float* __restrict__ nsy,
                                            const int*  __restrict__ lut_indices,
                                            const int*  __restrict__ lut_type,
                                            int n, int l) {
    int idx = __ldg(lut_indices + l);

    float sx = __ldg(nsx + idx);
    float sy = __ldg(nsy + idx);
    float cx = __ldg(pos + idx)     + 0.5f * sx;   // INV_STDX = 1
    float cy = __ldg(pos + n + idx) + 0.5f * sy;   // INV_STDY = 1

    int bx0 = __float2int_rd(cx) - EXT;
    int by0 = __float2int_rd(cy) - EXT;

    float gx[WW], gy[WW];
    axis_weights(cx, bx0, gx);
    axis_weights(cy, by0, gy);

    int ilo = max(0, -bx0), ihi = min(WW, NBX - bx0);
    int jlo = max(0, -by0), jhi = min(WW, NBY - by0);

    float area = sx * sy;
    int t = __ldg(lut_type + idx);
    float* plane = g_dem + t * XY;

    if (jlo == 0 && jhi == WW) {
#if __CUDA_ARCH__ >= 900
        int a  = by0 & 3;
        int b4 = by0 & ~3;
        float w[8];
        build_wpad(gy, a, w);
#pragma unroll
        for (int i = 0; i < WW; i++) {
            if (i < ilo || i >= ihi) continue;
            float wi = area * gx[i];
            float4* p = reinterpret_cast<float4*>(plane + (bx0 + i) * NBY + b4);
            atomicAdd(p,     make_float4(wi * w[0], wi * w[1], wi * w[2], wi * w[3]));
            atomicAdd(p + 1, make_float4(wi * w[4], wi * w[5], wi * w[6], wi * w[7]));
        }
#else
#pragma unroll
        for (int i = 0; i < WW; i++) {
            if (i < ilo || i >= ihi) continue;
            float wi = area * gx[i];
            float* row = plane + (bx0 + i) * NBY + by0;
#pragma unroll
            for (int j = 0; j < WW; j++) atomicAdd(row + j, wi * gy[j]);
        }
#endif
    } else {
#pragma unroll
        for (int i = 0; i < WW; i++) {
            if (i < ilo || i >= ihi) continue;
            float wi = area * gx[i];
            float* row = plane + (bx0 + i) * NBY + by0;
#pragma unroll
            for (int j = 0; j < WW; j++) {
                if (j < jlo || j >= jhi) continue;
                atomicAdd(row + j, wi * gy[j]);
            }
        }
    }
}

__global__ void __launch_bounds__(256)
scatter_kernel(const float* __restrict__ pos,
               const float* __restrict__ nsx,
               const float* __restrict__ nsy,
               const int*  __restrict__ lut_indices,
               const int*  __restrict__ lut_type,
               int n, int L, int H) {
    int l = blockIdx.x * blockDim.x + threadIdx.x;
    if (l >= H) return;
    scatter_one(pos, nsx, nsy, lut_indices, lut_type, n, l);
    int l2 = l + H;
    if (l2 < L)
        scatter_one(pos, nsx, nsy, lut_indices, lut_type, n, l2);
}

// ---------------------------------------------------------------------------
// Kernel 3: compat[t][xy] = sum_l frac[t][l] * dem[l][xy]   (6x6, tiny)
// ---------------------------------------------------------------------------
__global__ void compat_kernel(const int* __restrict__ frac) {
    int xy = blockIdx.x * blockDim.x + threadIdx.x;
    if (xy >= XY) return;
    float d[NBL];
#pragma unroll
    for (int l = 0; l < NBL; l++) d[l] = g_dem[l * XY + xy];
#pragma unroll
    for (int t = 0; t < NBL; t++) {
        float acc = 0.0f;
#pragma unroll
        for (int l = 0; l < NBL; l++)
            acc += d[l] * (float)__ldg(frac + t * NBL + l);
        g_compat[t * XY + xy] = acc;
    }
}

// ---------------------------------------------------------------------------
// One gather instance. Fast path: 2 x LDG.128 per row (window always fits
// in-row); zero-padded weights make extra lanes contribute exactly 0.
// ---------------------------------------------------------------------------
__device__ __forceinline__ void gather_one(const float* __restrict__ pos,
                                           const float* __restrict__ nsx,
                                           const float* __restrict__ nsy,
                                           const int*  __restrict__ lut_indices,
                                           const int*  __restrict__ lut_type,
                                           float* __restrict__ out,
                                           int n, int l) {
    int idx = __ldg(lut_indices + l);

    float sx = __ldg(nsx + idx);
    float sy = __ldg(nsy + idx);
    float cx = __ldg(pos + idx)     + 0.5f * sx;
    float cy = __ldg(pos + n + idx) + 0.5f * sy;

    int bx0 = __float2int_rd(cx) - EXT;
    int by0 = __float2int_rd(cy) - EXT;

    float gx[WW], gy[WW];
    axis_weights(cx, bx0, gx);
    axis_weights(cy, by0, gy);

    int ilo = max(0, -bx0), ihi = min(WW, NBX - bx0);
    int jlo = max(0, -by0), jhi = min(WW, NBY - by0);

    int t = __ldg(lut_type + idx);
    const float* plane = g_compat + t * XY;

    float acc = 0.0f;
    if (jlo == 0 && jhi == WW) {
        int a  = by0 & 3;
        int b4 = by0 & ~3;
        float w[8];
        build_wpad(gy, a, w);
#pragma unroll
        for (int i = 0; i < WW; i++) {
            if (i < ilo || i >= ihi) continue;
            const float4* p =
                reinterpret_cast<const float4*>(plane + (bx0 + i) * NBY + b4);
            float4 fA = __ldg(p);
            float4 fB = __ldg(p + 1);
            float ai = fA.x * w[0] + fA.y * w[1] + fA.z * w[2] + fA.w * w[3]
                     + fB.x * w[4] + fB.y * w[5] + fB.z * w[6] + fB.w * w[7];
            acc += gx[i] * ai;
        }
    } else {
#pragma unroll
        for (int i = 0; i < WW; i++) {
            if (i < ilo || i >= ihi) continue;
            const float* row = plane + (bx0 + i) * NBY + by0;
            float ai = 0.0f;
#pragma unroll
            for (int j = 0; j < WW; j++) {
                if (j < jlo || j >= jhi) continue;
                ai += gy[j] * __ldg(row + j);
            }
            acc += gx[i] * ai;
        }
    }

    // STDXY = 1, SLICE_CAPACITY = 16
    out[idx] = acc * (1.0f / 16.0f);
}

__global__ void __launch_bounds__(256)
gather_kernel(const float* __restrict__ pos,
              const float* __restrict__ nsx,
              const float* __restrict__ nsy,
              const int*  __restrict__ lut_indices,
              const int*  __restrict__ lut_type,
              float* __restrict__ out,
              int n, int L, int H) {
    int l = blockIdx.x * blockDim.x + threadIdx.x;
    if (l >= H) return;
    gather_one(pos, nsx, nsy, lut_indices, lut_type, out, n, l);
    int l2 = l + H;
    if (l2 < L)
        gather_one(pos, nsx, nsy, lut_indices, lut_type, out, n, l2);
}

// ---------------------------------------------------------------------------
extern "C" void kernel_launch(void* const* d_in, const int* in_sizes, int n_in,
                              void* d_out, int out_size) {
    const float* pos         = (const float*)d_in[0];
    const float* node_size_x = (const float*)d_in[1];
    const float* node_size_y = (const float*)d_in[2];
    const int*   lut_indices = (const int*)  d_in[3];
    const int*   lut_type    = (const int*)  d_in[4];
    const int*   lut_frac    = (const int*)  d_in[5];

    int n = in_sizes[1];   // number of nodes (N)
    int L = in_sizes[3];   // number of LUT instances
    int H = (L + 1) / 2;   // 2 instances per thread

    zero_kernel<<<1024, 256>>>((float4*)d_out, out_size / 4);

    int blocks = (H + 255) / 256;
    scatter_kernel<<<blocks, 256>>>(pos, node_size_x, node_size_y,
                                    lut_indices, lut_type, n, L, H);

    compat_kernel<<<(XY + 255) / 256, 256>>>(lut_frac);

    gather_kernel<<<blocks, 256>>>(pos, node_size_x, node_size_y,
                                   lut_indices, lut_type, (float*)d_out, n, L, H);
}